// round 4
// baseline (speedup 1.0000x reference)
#include <cuda_runtime.h>
#include <cuda_bf16.h>
#include <math.h>
#include <stdint.h>

// ---------------------------------------------------------------------------
// GPT Sparse Transformer Block  (B=2, S=2048, D=1024, H=16, Dh=64, HID=4096)
// Round 4: tf32 mma.sync GEMMs, cp.async 3-stage pipeline, BOTH operands via
// ldmatrix (weights pre-transposed+rounded to [N][K] at pack time).
// ---------------------------------------------------------------------------

#define D_MODEL 1024
#define N_HEADS 16
#define HEAD_DIM 64
#define HIDDEN 4096
#define SEQ 2048
#define BATCH 2
#define BLK 16
#define M_ROWS (BATCH * SEQ)   // 4096
#define QKV_LD (3 * D_MODEL)   // 3072

// ------------------------- scratch (no allocations allowed) ----------------
__device__ float g_h   [M_ROWS * D_MODEL];
__device__ float g_qkv [M_ROWS * QKV_LD];
__device__ float g_ctx [M_ROWS * D_MODEL];
__device__ float g_x1  [M_ROWS * D_MODEL];
__device__ float g_ff  [M_ROWS * HIDDEN];
// rounded, TRANSPOSED weights: [N][K]
__device__ float g_wqkv[QKV_LD * D_MODEL];
__device__ float g_bqkv[QKV_LD];
__device__ float g_wo_r[D_MODEL * D_MODEL];
__device__ float g_w1_r[HIDDEN * D_MODEL];
__device__ float g_w2_r[D_MODEL * HIDDEN];

// ------------------------------- helpers -----------------------------------
__device__ __forceinline__ uint32_t f2tf32(float x) {
    uint32_t r;
    asm("cvt.rna.tf32.f32 %0, %1;" : "=r"(r) : "f"(x));
    return r;
}
__device__ __forceinline__ float rtf(float x) { return __uint_as_float(f2tf32(x)); }

__device__ __forceinline__ void ldsm_x4(uint32_t* r, uint32_t addr) {
    asm volatile("ldmatrix.sync.aligned.m8n8.x4.shared.b16 {%0,%1,%2,%3}, [%4];"
                 : "=r"(r[0]), "=r"(r[1]), "=r"(r[2]), "=r"(r[3]) : "r"(addr));
}
__device__ __forceinline__ void mma_tf32(float* d, const uint32_t* a,
                                         uint32_t b0, uint32_t b1) {
    asm volatile(
        "mma.sync.aligned.m16n8k8.row.col.f32.tf32.tf32.f32 "
        "{%0,%1,%2,%3}, {%4,%5,%6,%7}, {%8,%9}, {%0,%1,%2,%3};"
        : "+f"(d[0]), "+f"(d[1]), "+f"(d[2]), "+f"(d[3])
        : "r"(a[0]), "r"(a[1]), "r"(a[2]), "r"(a[3]), "r"(b0), "r"(b1));
}
__device__ __forceinline__ void cp16(void* smem, const void* g) {
    uint32_t s = (uint32_t)__cvta_generic_to_shared(smem);
    asm volatile("cp.async.cg.shared.global [%0], [%1], 16;" :: "r"(s), "l"(g));
}
__device__ __forceinline__ void cp_commit() { asm volatile("cp.async.commit_group;"); }
__device__ __forceinline__ void cp_wait1()  { asm volatile("cp.async.wait_group 1;"); }

// ----------------- weight transpose + tf32-round kernel ----------------------
// src[K][N] row-major  ->  dst[N][K] row-major, rna-rounded.
// block (32,8), grid (N/32, K/32).
__global__ void __launch_bounds__(256) trt_kernel(
    const float* __restrict__ src, float* __restrict__ dst, int K, int N)
{
    __shared__ float t[32][33];
    int n0 = blockIdx.x * 32;
    int k0 = blockIdx.y * 32;
    int tx = threadIdx.x, ty = threadIdx.y;
    #pragma unroll
    for (int r = 0; r < 32; r += 8)
        t[ty + r][tx] = src[(size_t)(k0 + ty + r) * N + n0 + tx];
    __syncthreads();
    #pragma unroll
    for (int r = 0; r < 32; r += 8)
        dst[(size_t)(n0 + ty + r) * K + k0 + tx] = rtf(t[tx][ty + r]);
}

// ------------------------------- LayerNorm ----------------------------------
__global__ void __launch_bounds__(256) ln_kernel(
    const float* __restrict__ x, const float* __restrict__ gg,
    const float* __restrict__ bb, float* __restrict__ out)
{
    __shared__ float red[2][8];
    int row = blockIdx.x;
    int tid = threadIdx.x;
    const float4* xr = reinterpret_cast<const float4*>(x + (size_t)row * D_MODEL);
    float4 v = xr[tid];
    float s  = v.x + v.y + v.z + v.w;
    float sq = v.x*v.x + v.y*v.y + v.z*v.z + v.w*v.w;
    #pragma unroll
    for (int o = 16; o; o >>= 1) {
        s  += __shfl_xor_sync(0xFFFFFFFFu, s,  o);
        sq += __shfl_xor_sync(0xFFFFFFFFu, sq, o);
    }
    if ((tid & 31) == 0) { red[0][tid >> 5] = s; red[1][tid >> 5] = sq; }
    __syncthreads();
    if (tid < 32) {
        float a  = (tid < 8) ? red[0][tid] : 0.f;
        float b2 = (tid < 8) ? red[1][tid] : 0.f;
        #pragma unroll
        for (int o = 4; o; o >>= 1) {
            a  += __shfl_xor_sync(0xFFFFFFFFu, a,  o);
            b2 += __shfl_xor_sync(0xFFFFFFFFu, b2, o);
        }
        if (tid == 0) { red[0][0] = a; red[1][0] = b2; }
    }
    __syncthreads();
    float mean = red[0][0] * (1.f / D_MODEL);
    float var  = red[1][0] * (1.f / D_MODEL) - mean * mean;
    float inv  = rsqrtf(var + 1e-5f);
    float4 g4 = reinterpret_cast<const float4*>(gg)[tid];
    float4 b4 = reinterpret_cast<const float4*>(bb)[tid];
    float4 o4;
    o4.x = rtf((v.x - mean) * inv * g4.x + b4.x);
    o4.y = rtf((v.y - mean) * inv * g4.y + b4.y);
    o4.z = rtf((v.z - mean) * inv * g4.z + b4.z);
    o4.w = rtf((v.w - mean) * inv * g4.w + b4.w);
    reinterpret_cast<float4*>(out + (size_t)row * D_MODEL)[tid] = o4;
}

// --------------------------- tf32 tensor GEMM v4 -----------------------------
// C[M,N] = A[M,K] @ Bt^T + bias,  Bt is [N][K] (transposed weights, ld = K).
// EPI 0: bias, 1: bias+res, 2: bias+GELU(->tf32 round).
// Block 128x128x32, 4 warps m64n64, 3-stage cp.async, both operands via ldsm.
template <int EPI>
__global__ void __launch_bounds__(128) tgemm_kernel(
    const float* __restrict__ A, const float* __restrict__ Bt,
    const float* __restrict__ bias, const float* __restrict__ res,
    float* __restrict__ C, int M, int N, int K)
{
    constexpr int BM = 128, BN = 128, BK = 32, STAGES = 3;
    constexpr int LDA = 36;   // 144B rows; LDSM & STS conflict-free
    extern __shared__ float sm[];
    float* As = sm;                           // [STAGES][BM][LDA]
    float* Bs = sm + STAGES * BM * LDA;       // [STAGES][BN][LDA]

    const int tid  = threadIdx.x;
    const int wid  = tid >> 5;
    const int lane = tid & 31;
    const int bm = blockIdx.y * BM;
    const int bn = blockIdx.x * BN;
    const int wm = (wid >> 1) * 64;
    const int wn = (wid & 1) * 64;

    const int l_row = tid >> 3;          // 0..15 (+16r)
    const int l_kc  = (tid & 7) * 4;
    const float* Ag = A  + (size_t)(bm + l_row) * K + l_kc;
    const float* Bg = Bt + (size_t)(bn + l_row) * K + l_kc;

    float acc[4][8][4];
    #pragma unroll
    for (int i = 0; i < 4; i++)
        #pragma unroll
        for (int j = 0; j < 8; j++)
            #pragma unroll
            for (int r = 0; r < 4; r++) acc[i][j][r] = 0.f;

    auto load_stage = [&](int stage, int k0) {
        float* Ad = As + stage * (BM * LDA);
        float* Bd = Bs + stage * (BN * LDA);
        #pragma unroll
        for (int r = 0; r < 8; r++)
            cp16(&Ad[(l_row + 16 * r) * LDA + l_kc], Ag + (size_t)(16 * r) * K + k0);
        #pragma unroll
        for (int r = 0; r < 8; r++)
            cp16(&Bd[(l_row + 16 * r) * LDA + l_kc], Bg + (size_t)(16 * r) * K + k0);
    };

    const int NIT = K / BK;
    load_stage(0, 0);   cp_commit();
    load_stage(1, BK);  cp_commit();

    const int lr = lane & 15;
    const int lh = lane >> 4;

    for (int it = 0; it < NIT; ++it) {
        cp_wait1();
        __syncthreads();
        if (it + 2 < NIT) load_stage((it + 2) % STAGES, (it + 2) * BK);
        cp_commit();

        const uint32_t a_base = (uint32_t)__cvta_generic_to_shared(
            As + (it % STAGES) * (BM * LDA));
        const uint32_t b_base = (uint32_t)__cvta_generic_to_shared(
            Bs + (it % STAGES) * (BN * LDA));

        #pragma unroll
        for (int ks = 0; ks < 4; ks++) {
            uint32_t af[4][4], bf[4][4];
            #pragma unroll
            for (int mt = 0; mt < 4; mt++)
                ldsm_x4(af[mt], a_base +
                    ((uint32_t)((wm + mt * 16 + lr) * LDA + ks * 8 + lh * 4) << 2));
            #pragma unroll
            for (int np = 0; np < 4; np++)
                ldsm_x4(bf[np], b_base +
                    ((uint32_t)((wn + np * 16 + lr) * LDA + ks * 8 + lh * 4) << 2));
            #pragma unroll
            for (int mt = 0; mt < 4; mt++) {
                #pragma unroll
                for (int np = 0; np < 4; np++) {
                    mma_tf32(acc[mt][2 * np + 0], af[mt], bf[np][0], bf[np][2]);
                    mma_tf32(acc[mt][2 * np + 1], af[mt], bf[np][1], bf[np][3]);
                }
            }
        }
        __syncthreads();
    }

    // ---- epilogue ----
    const int qr = lane >> 2;
    const int qc = 2 * (lane & 3);
    #pragma unroll
    for (int mt = 0; mt < 4; mt++) {
        int r0 = bm + wm + mt * 16 + qr;
        #pragma unroll
        for (int nt = 0; nt < 8; nt++) {
            int col = bn + wn + nt * 8 + qc;
            float2 bv = *reinterpret_cast<const float2*>(&bias[col]);
            float v0 = acc[mt][nt][0] + bv.x;
            float v1 = acc[mt][nt][1] + bv.y;
            float v2 = acc[mt][nt][2] + bv.x;
            float v3 = acc[mt][nt][3] + bv.y;
            if (EPI == 1) {
                float2 r0v = *reinterpret_cast<const float2*>(&res[(size_t)r0 * N + col]);
                float2 r1v = *reinterpret_cast<const float2*>(&res[(size_t)(r0 + 8) * N + col]);
                v0 += r0v.x; v1 += r0v.y; v2 += r1v.x; v3 += r1v.y;
            }
            if (EPI == 2) {
                v0 = rtf(0.5f * v0 * (1.f + erff(v0 * 0.70710678118654752f)));
                v1 = rtf(0.5f * v1 * (1.f + erff(v1 * 0.70710678118654752f)));
                v2 = rtf(0.5f * v2 * (1.f + erff(v2 * 0.70710678118654752f)));
                v3 = rtf(0.5f * v3 * (1.f + erff(v3 * 0.70710678118654752f)));
            }
            *reinterpret_cast<float2*>(&C[(size_t)r0 * N + col])       = make_float2(v0, v1);
            *reinterpret_cast<float2*>(&C[(size_t)(r0 + 8) * N + col]) = make_float2(v2, v3);
        }
    }
}

// ---------------------------- sparse attention ------------------------------
__global__ void __launch_bounds__(128) sparse_attn_kernel(
    const float* __restrict__ QKV, float* __restrict__ O)
{
    __shared__ float q_s[4][64];
    __shared__ float p_s[4][160];

    int w    = threadIdx.x >> 5;
    int lane = threadIdx.x & 31;
    int gw   = blockIdx.x * 4 + w;
    int i    = gw & (SEQ - 1);
    int bh   = gw >> 11;
    int h    = bh & (N_HEADS - 1);
    int b    = bh >> 4;

    size_t rowq = (size_t)(b * SEQ + i) * QKV_LD + h * HEAD_DIM;
    q_s[w][lane]      = QKV[rowq + lane];
    q_s[w][lane + 32] = QKV[rowq + lane + 32];
    __syncwarp();

    int lb   = i & ~(BLK - 1);
    int nloc = (i & (BLK - 1)) + 1;
    int nsum = i >> 4;
    int nk   = nloc + nsum;

    float sc[5];
    float mymax = -1e30f;
    #pragma unroll
    for (int c = 0; c < 5; c++) {
        int t = lane + c * 32;
        if (t < nk) {
            int j = (t < nloc) ? (lb + t) : (((t - nloc) << 4) + 15);
            const float4* kp = reinterpret_cast<const float4*>(
                QKV + (size_t)(b * SEQ + j) * QKV_LD + D_MODEL + h * HEAD_DIM);
            float dot = 0.f;
            #pragma unroll
            for (int d = 0; d < 16; d++) {
                float4 kv = kp[d];
                dot = fmaf(kv.x, q_s[w][d * 4 + 0], dot);
                dot = fmaf(kv.y, q_s[w][d * 4 + 1], dot);
                dot = fmaf(kv.z, q_s[w][d * 4 + 2], dot);
                dot = fmaf(kv.w, q_s[w][d * 4 + 3], dot);
            }
            sc[c] = dot * 0.125f;
            mymax = fmaxf(mymax, sc[c]);
        }
    }
    #pragma unroll
    for (int o = 16; o; o >>= 1)
        mymax = fmaxf(mymax, __shfl_xor_sync(0xFFFFFFFFu, mymax, o));

    float mysum = 0.f;
    #pragma unroll
    for (int c = 0; c < 5; c++) {
        int t = lane + c * 32;
        if (t < nk) { sc[c] = __expf(sc[c] - mymax); mysum += sc[c]; }
    }
    #pragma unroll
    for (int o = 16; o; o >>= 1)
        mysum += __shfl_xor_sync(0xFFFFFFFFu, mysum, o);
    float inv = 1.f / mysum;

    #pragma unroll
    for (int c = 0; c < 5; c++) {
        int t = lane + c * 32;
        if (t < nk) p_s[w][t] = sc[c] * inv;
    }
    __syncwarp();

    float acc0 = 0.f, acc1 = 0.f;
    for (int t = 0; t < nk; t++) {
        int j = (t < nloc) ? (lb + t) : (((t - nloc) << 4) + 15);
        const float* vp = QKV + (size_t)(b * SEQ + j) * QKV_LD + 2 * D_MODEL + h * HEAD_DIM;
        float p = p_s[w][t];
        acc0 = fmaf(p, vp[lane],      acc0);
        acc1 = fmaf(p, vp[lane + 32], acc1);
    }
    size_t baseo = (size_t)(b * SEQ + i) * D_MODEL + h * HEAD_DIM;
    O[baseo + lane]      = rtf(acc0);
    O[baseo + lane + 32] = rtf(acc1);
}

// -------------------------------- launch ------------------------------------
static float* sym_addr(const void* sym) {
    void* p = nullptr;
    cudaGetSymbolAddress(&p, sym);
    return reinterpret_cast<float*>(p);
}

extern "C" void kernel_launch(void* const* d_in, const int* in_sizes, int n_in,
                              void* d_out, int out_size)
{
    const float* x     = (const float*)d_in[0];
    const float* ln1_g = (const float*)d_in[1];
    const float* ln1_b = (const float*)d_in[2];
    const float* wq    = (const float*)d_in[3];
    const float* bq    = (const float*)d_in[4];
    const float* wk    = (const float*)d_in[5];
    const float* bk    = (const float*)d_in[6];
    const float* wv    = (const float*)d_in[7];
    const float* bv    = (const float*)d_in[8];
    const float* wo    = (const float*)d_in[9];
    const float* bo    = (const float*)d_in[10];
    const float* ln2_g = (const float*)d_in[11];
    const float* ln2_b = (const float*)d_in[12];
    const float* w1    = (const float*)d_in[13];
    const float* b1    = (const float*)d_in[14];
    const float* w2    = (const float*)d_in[15];
    const float* b2    = (const float*)d_in[16];
    float* out = (float*)d_out;

    float* p_h    = sym_addr(g_h);
    float* p_qkv  = sym_addr(g_qkv);
    float* p_ctx  = sym_addr(g_ctx);
    float* p_x1   = sym_addr(g_x1);
    float* p_ff   = sym_addr(g_ff);
    float* p_wqkv = sym_addr(g_wqkv);
    float* p_bqkv = sym_addr(g_bqkv);
    float* p_wo   = sym_addr(g_wo_r);
    float* p_w1   = sym_addr(g_w1_r);
    float* p_w2   = sym_addr(g_w2_r);

    const int M = M_ROWS;
    constexpr int SMEM_BYTES = 3 * (128 + 128) * 36 * (int)sizeof(float); // 110,592

    cudaFuncSetAttribute(tgemm_kernel<0>, cudaFuncAttributeMaxDynamicSharedMemorySize, SMEM_BYTES);
    cudaFuncSetAttribute(tgemm_kernel<1>, cudaFuncAttributeMaxDynamicSharedMemorySize, SMEM_BYTES);
    cudaFuncSetAttribute(tgemm_kernel<2>, cudaFuncAttributeMaxDynamicSharedMemorySize, SMEM_BYTES);

    // ---- transpose + round weights into [N][K] scratch ----
    dim3 tb(32, 8);
    trt_kernel<<<dim3(D_MODEL / 32, D_MODEL / 32), tb>>>(wq, p_wqkv + 0 * D_MODEL * D_MODEL, D_MODEL, D_MODEL);
    trt_kernel<<<dim3(D_MODEL / 32, D_MODEL / 32), tb>>>(wk, p_wqkv + 1 * D_MODEL * D_MODEL, D_MODEL, D_MODEL);
    trt_kernel<<<dim3(D_MODEL / 32, D_MODEL / 32), tb>>>(wv, p_wqkv + 2 * D_MODEL * D_MODEL, D_MODEL, D_MODEL);
    trt_kernel<<<dim3(D_MODEL / 32, D_MODEL / 32), tb>>>(wo, p_wo, D_MODEL, D_MODEL);
    trt_kernel<<<dim3(HIDDEN / 32,  D_MODEL / 32), tb>>>(w1, p_w1, D_MODEL, HIDDEN);
    trt_kernel<<<dim3(D_MODEL / 32, HIDDEN / 32),  tb>>>(w2, p_w2, HIDDEN, D_MODEL);
    cudaMemcpyAsync(p_bqkv,               bq, D_MODEL * sizeof(float), cudaMemcpyDeviceToDevice, 0);
    cudaMemcpyAsync(p_bqkv + D_MODEL,     bk, D_MODEL * sizeof(float), cudaMemcpyDeviceToDevice, 0);
    cudaMemcpyAsync(p_bqkv + 2 * D_MODEL, bv, D_MODEL * sizeof(float), cudaMemcpyDeviceToDevice, 0);

    // ---- LN1 ----
    ln_kernel<<<M, 256>>>(x, ln1_g, ln1_b, p_h);

    // ---- fused QKV ----
    dim3 gQKV(QKV_LD / 128, M / 128);
    tgemm_kernel<0><<<gQKV, 128, SMEM_BYTES>>>(p_h, p_wqkv, p_bqkv, nullptr,
                                               p_qkv, M, QKV_LD, D_MODEL);

    // ---- sparse attention ----
    sparse_attn_kernel<<<(BATCH * N_HEADS * SEQ) / 4, 128>>>(p_qkv, p_ctx);

    // ---- Wo + residual ----
    dim3 gD(D_MODEL / 128, M / 128);
    tgemm_kernel<1><<<gD, 128, SMEM_BYTES>>>(p_ctx, p_wo, bo, x, p_x1,
                                             M, D_MODEL, D_MODEL);

    // ---- LN2 ----
    ln_kernel<<<M, 256>>>(p_x1, ln2_g, ln2_b, p_h);

    // ---- FFN ----
    dim3 gH(HIDDEN / 128, M / 128);
    tgemm_kernel<2><<<gH, 128, SMEM_BYTES>>>(p_h, p_w1, b1, nullptr, p_ff,
                                             M, HIDDEN, D_MODEL);
    tgemm_kernel<1><<<gD, 128, SMEM_BYTES>>>(p_ff, p_w2, b2, p_x1, out,
                                             M, D_MODEL, HIDDEN);
}

// round 7
// speedup vs baseline: 1.0811x; 1.0811x over previous
#include <cuda_runtime.h>
#include <cuda_bf16.h>
#include <math.h>
#include <stdint.h>

// ---------------------------------------------------------------------------
// GPT Sparse Transformer Block  (B=2, S=2048, D=1024, H=16, Dh=64, HID=4096)
// Round 7 (= Round 6 resubmit after infra failure): tf32 mma.sync GEMMs,
// 3-stage cp.async, 256 threads / 8 warps per CTA (warp tile m32n64).
// tcgen05 unavailable (harness PTX target = compute_100).
// ---------------------------------------------------------------------------

#define D_MODEL 1024
#define N_HEADS 16
#define HEAD_DIM 64
#define HIDDEN 4096
#define SEQ 2048
#define BATCH 2
#define BLK 16
#define M_ROWS (BATCH * SEQ)   // 4096
#define QKV_LD (3 * D_MODEL)   // 3072

// ------------------------- scratch (no allocations allowed) ----------------
__device__ float g_h   [M_ROWS * D_MODEL];        // LN output (tf32-rounded)
__device__ float g_qkv [M_ROWS * QKV_LD];         // fused q|k|v
__device__ float g_ctx [M_ROWS * D_MODEL];        // attn out (tf32-rounded)
__device__ float g_x1  [M_ROWS * D_MODEL];        // after attention residual
__device__ float g_ff  [M_ROWS * HIDDEN];         // GELU out (tf32-rounded)
// rounded weight copies, [K][N] layout
__device__ float g_wqkv[D_MODEL * QKV_LD];        // wq|wk|wv rounded
__device__ float g_bqkv[QKV_LD];
__device__ float g_wo_r[D_MODEL * D_MODEL];
__device__ float g_w1_r[D_MODEL * HIDDEN];
__device__ float g_w2_r[HIDDEN * D_MODEL];

// ------------------------------- helpers -----------------------------------
__device__ __forceinline__ uint32_t f2tf32(float x) {
    uint32_t r;
    asm("cvt.rna.tf32.f32 %0, %1;" : "=r"(r) : "f"(x));
    return r;
}
__device__ __forceinline__ float rtf(float x) { return __uint_as_float(f2tf32(x)); }

__device__ __forceinline__ void ldsm_x4(uint32_t* r, uint32_t addr) {
    asm volatile("ldmatrix.sync.aligned.m8n8.x4.shared.b16 {%0,%1,%2,%3}, [%4];"
                 : "=r"(r[0]), "=r"(r[1]), "=r"(r[2]), "=r"(r[3]) : "r"(addr));
}
__device__ __forceinline__ void mma_tf32(float* d, const uint32_t* a,
                                         uint32_t b0, uint32_t b1) {
    asm volatile(
        "mma.sync.aligned.m16n8k8.row.col.f32.tf32.tf32.f32 "
        "{%0,%1,%2,%3}, {%4,%5,%6,%7}, {%8,%9}, {%0,%1,%2,%3};"
        : "+f"(d[0]), "+f"(d[1]), "+f"(d[2]), "+f"(d[3])
        : "r"(a[0]), "r"(a[1]), "r"(a[2]), "r"(a[3]), "r"(b0), "r"(b1));
}
__device__ __forceinline__ void cp16(void* smem, const void* g) {
    uint32_t s = (uint32_t)__cvta_generic_to_shared(smem);
    asm volatile("cp.async.cg.shared.global [%0], [%1], 16;" :: "r"(s), "l"(g));
}
__device__ __forceinline__ void cp_commit() { asm volatile("cp.async.commit_group;"); }
__device__ __forceinline__ void cp_wait1()  { asm volatile("cp.async.wait_group 1;"); }

// --------------------- weight round/pack kernel ------------------------------
__global__ void __launch_bounds__(256) round_pack_kernel(
    const float4* __restrict__ src, float4* __restrict__ dst,
    int cols4, int dstLd4)
{
    int r = blockIdx.x;
    int c = blockIdx.y * 256 + threadIdx.x;
    float4 v = src[(size_t)r * cols4 + c];
    v.x = rtf(v.x); v.y = rtf(v.y); v.z = rtf(v.z); v.w = rtf(v.w);
    dst[(size_t)r * dstLd4 + c] = v;
}

// ------------------------------- LayerNorm ----------------------------------
__global__ void __launch_bounds__(256) ln_kernel(
    const float* __restrict__ x, const float* __restrict__ gg,
    const float* __restrict__ bb, float* __restrict__ out)
{
    __shared__ float red[2][8];
    int row = blockIdx.x;
    int tid = threadIdx.x;
    const float4* xr = reinterpret_cast<const float4*>(x + (size_t)row * D_MODEL);
    float4 v = xr[tid];
    float s  = v.x + v.y + v.z + v.w;
    float sq = v.x*v.x + v.y*v.y + v.z*v.z + v.w*v.w;
    #pragma unroll
    for (int o = 16; o; o >>= 1) {
        s  += __shfl_xor_sync(0xFFFFFFFFu, s,  o);
        sq += __shfl_xor_sync(0xFFFFFFFFu, sq, o);
    }
    if ((tid & 31) == 0) { red[0][tid >> 5] = s; red[1][tid >> 5] = sq; }
    __syncthreads();
    if (tid < 32) {
        float a  = (tid < 8) ? red[0][tid] : 0.f;
        float b2 = (tid < 8) ? red[1][tid] : 0.f;
        #pragma unroll
        for (int o = 4; o; o >>= 1) {
            a  += __shfl_xor_sync(0xFFFFFFFFu, a,  o);
            b2 += __shfl_xor_sync(0xFFFFFFFFu, b2, o);
        }
        if (tid == 0) { red[0][0] = a; red[1][0] = b2; }
    }
    __syncthreads();
    float mean = red[0][0] * (1.f / D_MODEL);
    float var  = red[1][0] * (1.f / D_MODEL) - mean * mean;
    float inv  = rsqrtf(var + 1e-5f);
    float4 g4 = reinterpret_cast<const float4*>(gg)[tid];
    float4 b4 = reinterpret_cast<const float4*>(bb)[tid];
    float4 o4;
    o4.x = rtf((v.x - mean) * inv * g4.x + b4.x);
    o4.y = rtf((v.y - mean) * inv * g4.y + b4.y);
    o4.z = rtf((v.z - mean) * inv * g4.z + b4.z);
    o4.w = rtf((v.w - mean) * inv * g4.w + b4.w);
    reinterpret_cast<float4*>(out + (size_t)row * D_MODEL)[tid] = o4;
}

// --------------------------- tf32 tensor GEMM v6 -----------------------------
// C[M,N] = A[M,K] @ B[K,N] + bias   (EPI 0: bias, 1: bias+res, 2: bias+GELU)
// Block 128x128x32, 256 threads / 8 warps (4 m-rows x 2 n-cols of m32n64),
// 3-stage cp.async pipeline. A, B pre-rounded to tf32.
template <int EPI>
__global__ void __launch_bounds__(256, 2) tgemm_kernel(
    const float* __restrict__ A, const float* __restrict__ B,
    const float* __restrict__ bias, const float* __restrict__ res,
    float* __restrict__ C, int M, int N, int K)
{
    constexpr int BM = 128, BN = 128, BK = 32, STAGES = 3;
    constexpr int LDA = 36;    // floats; LDSM & STS conflict-free
    constexpr int LDB = 136;   // floats; 136 mod 32 = 8 -> LDS conflict-free
    extern __shared__ float sm[];
    float* As = sm;                          // [STAGES][BM][LDA]
    float* Bs = sm + STAGES * BM * LDA;      // [STAGES][BK][LDB]

    const int tid  = threadIdx.x;
    const int wid  = tid >> 5;
    const int lane = tid & 31;
    const int bm = blockIdx.y * BM;
    const int bn = blockIdx.x * BN;
    const int wm = (wid >> 1) * 32;   // 0,32,64,96
    const int wn = (wid & 1) * 64;    // 0,64

    // loader lanes (256 threads)
    const int a_row = tid >> 3;          // 0..31 (+32r, r<4)
    const int a_kc  = (tid & 7) * 4;
    const int b_k   = tid >> 5;          // 0..7 (+8r, r<4)
    const int b_nc  = (tid & 31) * 4;
    const float* Ag = A + (size_t)(bm + a_row) * K + a_kc;
    const float* Bg = B + (size_t)b_k * N + bn + b_nc;

    float acc[2][8][4];
    #pragma unroll
    for (int i = 0; i < 2; i++)
        #pragma unroll
        for (int j = 0; j < 8; j++)
            #pragma unroll
            for (int r = 0; r < 4; r++) acc[i][j][r] = 0.f;

    auto load_stage = [&](int stage, int k0) {
        float* Ad = As + stage * (BM * LDA);
        float* Bd = Bs + stage * (BK * LDB);
        #pragma unroll
        for (int r = 0; r < 4; r++)
            cp16(&Ad[(a_row + 32 * r) * LDA + a_kc], Ag + (size_t)(32 * r) * K + k0);
        #pragma unroll
        for (int r = 0; r < 4; r++)
            cp16(&Bd[(b_k + 8 * r) * LDB + b_nc], Bg + (size_t)(k0 + 8 * r) * N);
    };

    const int NIT = K / BK;
    load_stage(0, 0);   cp_commit();
    load_stage(1, BK);  cp_commit();

    const int lr = lane & 15;
    const int lh = lane >> 4;
    const int kq = lane & 3;
    const int nq = lane >> 2;

    for (int it = 0; it < NIT; ++it) {
        cp_wait1();
        __syncthreads();
        if (it + 2 < NIT) load_stage((it + 2) % STAGES, (it + 2) * BK);
        cp_commit();

        const float* Ast = As + (it % STAGES) * (BM * LDA);
        const float* Bst = Bs + (it % STAGES) * (BK * LDB);
        const uint32_t a_base = (uint32_t)__cvta_generic_to_shared(Ast);

        #pragma unroll
        for (int ks = 0; ks < 4; ks++) {
            uint32_t af[2][4];
            #pragma unroll
            for (int mt = 0; mt < 2; mt++)
                ldsm_x4(af[mt], a_base +
                    ((uint32_t)((wm + mt * 16 + lr) * LDA + ks * 8 + lh * 4) << 2));
            uint32_t bf0[8], bf1[8];
            #pragma unroll
            for (int nt = 0; nt < 8; nt++) {
                bf0[nt] = __float_as_uint(Bst[(ks * 8 + kq)     * LDB + wn + nt * 8 + nq]);
                bf1[nt] = __float_as_uint(Bst[(ks * 8 + kq + 4) * LDB + wn + nt * 8 + nq]);
            }
            #pragma unroll
            for (int mt = 0; mt < 2; mt++)
                #pragma unroll
                for (int nt = 0; nt < 8; nt++)
                    mma_tf32(acc[mt][nt], af[mt], bf0[nt], bf1[nt]);
        }
        __syncthreads();
    }

    // ---- epilogue ----
    const int qr = lane >> 2;
    const int qc = 2 * (lane & 3);
    #pragma unroll
    for (int mt = 0; mt < 2; mt++) {
        int r0 = bm + wm + mt * 16 + qr;
        #pragma unroll
        for (int nt = 0; nt < 8; nt++) {
            int col = bn + wn + nt * 8 + qc;
            float2 bv = *reinterpret_cast<const float2*>(&bias[col]);
            float v0 = acc[mt][nt][0] + bv.x;
            float v1 = acc[mt][nt][1] + bv.y;
            float v2 = acc[mt][nt][2] + bv.x;
            float v3 = acc[mt][nt][3] + bv.y;
            if (EPI == 1) {
                float2 r0v = *reinterpret_cast<const float2*>(&res[(size_t)r0 * N + col]);
                float2 r1v = *reinterpret_cast<const float2*>(&res[(size_t)(r0 + 8) * N + col]);
                v0 += r0v.x; v1 += r0v.y; v2 += r1v.x; v3 += r1v.y;
            }
            if (EPI == 2) {
                v0 = rtf(0.5f * v0 * (1.f + erff(v0 * 0.70710678118654752f)));
                v1 = rtf(0.5f * v1 * (1.f + erff(v1 * 0.70710678118654752f)));
                v2 = rtf(0.5f * v2 * (1.f + erff(v2 * 0.70710678118654752f)));
                v3 = rtf(0.5f * v3 * (1.f + erff(v3 * 0.70710678118654752f)));
            }
            *reinterpret_cast<float2*>(&C[(size_t)r0 * N + col])       = make_float2(v0, v1);
            *reinterpret_cast<float2*>(&C[(size_t)(r0 + 8) * N + col]) = make_float2(v2, v3);
        }
    }
}

// ---------------------------- sparse attention ------------------------------
__global__ void __launch_bounds__(128) sparse_attn_kernel(
    const float* __restrict__ QKV, float* __restrict__ O)
{
    __shared__ float q_s[4][64];
    __shared__ float p_s[4][160];

    int w    = threadIdx.x >> 5;
    int lane = threadIdx.x & 31;
    int gw   = blockIdx.x * 4 + w;
    int i    = gw & (SEQ - 1);
    int bh   = gw >> 11;
    int h    = bh & (N_HEADS - 1);
    int b    = bh >> 4;

    size_t rowq = (size_t)(b * SEQ + i) * QKV_LD + h * HEAD_DIM;
    q_s[w][lane]      = QKV[rowq + lane];
    q_s[w][lane + 32] = QKV[rowq + lane + 32];
    __syncwarp();

    int lb   = i & ~(BLK - 1);
    int nloc = (i & (BLK - 1)) + 1;
    int nsum = i >> 4;
    int nk   = nloc + nsum;

    float sc[5];
    float mymax = -1e30f;
    #pragma unroll
    for (int c = 0; c < 5; c++) {
        int t = lane + c * 32;
        if (t < nk) {
            int j = (t < nloc) ? (lb + t) : (((t - nloc) << 4) + 15);
            const float4* kp = reinterpret_cast<const float4*>(
                QKV + (size_t)(b * SEQ + j) * QKV_LD + D_MODEL + h * HEAD_DIM);
            float dot = 0.f;
            #pragma unroll
            for (int d = 0; d < 16; d++) {
                float4 kv = kp[d];
                dot = fmaf(kv.x, q_s[w][d * 4 + 0], dot);
                dot = fmaf(kv.y, q_s[w][d * 4 + 1], dot);
                dot = fmaf(kv.z, q_s[w][d * 4 + 2], dot);
                dot = fmaf(kv.w, q_s[w][d * 4 + 3], dot);
            }
            sc[c] = dot * 0.125f;
            mymax = fmaxf(mymax, sc[c]);
        }
    }
    #pragma unroll
    for (int o = 16; o; o >>= 1)
        mymax = fmaxf(mymax, __shfl_xor_sync(0xFFFFFFFFu, mymax, o));

    float mysum = 0.f;
    #pragma unroll
    for (int c = 0; c < 5; c++) {
        int t = lane + c * 32;
        if (t < nk) { sc[c] = __expf(sc[c] - mymax); mysum += sc[c]; }
    }
    #pragma unroll
    for (int o = 16; o; o >>= 1)
        mysum += __shfl_xor_sync(0xFFFFFFFFu, mysum, o);
    float inv = 1.f / mysum;

    #pragma unroll
    for (int c = 0; c < 5; c++) {
        int t = lane + c * 32;
        if (t < nk) p_s[w][t] = sc[c] * inv;
    }
    __syncwarp();

    float acc0 = 0.f, acc1 = 0.f;
    for (int t = 0; t < nk; t++) {
        int j = (t < nloc) ? (lb + t) : (((t - nloc) << 4) + 15);
        const float* vp = QKV + (size_t)(b * SEQ + j) * QKV_LD + 2 * D_MODEL + h * HEAD_DIM;
        float p = p_s[w][t];
        acc0 = fmaf(p, vp[lane],      acc0);
        acc1 = fmaf(p, vp[lane + 32], acc1);
    }
    size_t baseo = (size_t)(b * SEQ + i) * D_MODEL + h * HEAD_DIM;
    O[baseo + lane]      = rtf(acc0);
    O[baseo + lane + 32] = rtf(acc1);
}

// -------------------------------- launch ------------------------------------
static float* sym_addr(const void* sym) {
    void* p = nullptr;
    cudaGetSymbolAddress(&p, sym);
    return reinterpret_cast<float*>(p);
}

extern "C" void kernel_launch(void* const* d_in, const int* in_sizes, int n_in,
                              void* d_out, int out_size)
{
    const float* x     = (const float*)d_in[0];
    const float* ln1_g = (const float*)d_in[1];
    const float* ln1_b = (const float*)d_in[2];
    const float* wq    = (const float*)d_in[3];
    const float* bq    = (const float*)d_in[4];
    const float* wk    = (const float*)d_in[5];
    const float* bk    = (const float*)d_in[6];
    const float* wv    = (const float*)d_in[7];
    const float* bv    = (const float*)d_in[8];
    const float* wo    = (const float*)d_in[9];
    const float* bo    = (const float*)d_in[10];
    const float* ln2_g = (const float*)d_in[11];
    const float* ln2_b = (const float*)d_in[12];
    const float* w1    = (const float*)d_in[13];
    const float* b1    = (const float*)d_in[14];
    const float* w2    = (const float*)d_in[15];
    const float* b2    = (const float*)d_in[16];
    float* out = (float*)d_out;

    float* p_h    = sym_addr(g_h);
    float* p_qkv  = sym_addr(g_qkv);
    float* p_ctx  = sym_addr(g_ctx);
    float* p_x1   = sym_addr(g_x1);
    float* p_ff   = sym_addr(g_ff);
    float* p_wqkv = sym_addr(g_wqkv);
    float* p_bqkv = sym_addr(g_bqkv);
    float* p_wo   = sym_addr(g_wo_r);
    float* p_w1   = sym_addr(g_w1_r);
    float* p_w2   = sym_addr(g_w2_r);

    const int M = M_ROWS;
    constexpr int SMEM_BYTES =
        (3 * 128 * 36 + 3 * 32 * 136) * (int)sizeof(float);  // 107,520 B

    cudaFuncSetAttribute(tgemm_kernel<0>, cudaFuncAttributeMaxDynamicSharedMemorySize, SMEM_BYTES);
    cudaFuncSetAttribute(tgemm_kernel<1>, cudaFuncAttributeMaxDynamicSharedMemorySize, SMEM_BYTES);
    cudaFuncSetAttribute(tgemm_kernel<2>, cudaFuncAttributeMaxDynamicSharedMemorySize, SMEM_BYTES);

    // ---- round + pack weights ([K][N], qkv concatenated) ----
    round_pack_kernel<<<dim3(D_MODEL, 1), 256>>>(
        (const float4*)wq, (float4*)(p_wqkv + 0),            D_MODEL / 4, QKV_LD / 4);
    round_pack_kernel<<<dim3(D_MODEL, 1), 256>>>(
        (const float4*)wk, (float4*)(p_wqkv + D_MODEL),      D_MODEL / 4, QKV_LD / 4);
    round_pack_kernel<<<dim3(D_MODEL, 1), 256>>>(
        (const float4*)wv, (float4*)(p_wqkv + 2 * D_MODEL),  D_MODEL / 4, QKV_LD / 4);
    round_pack_kernel<<<dim3(D_MODEL, 1), 256>>>(
        (const float4*)wo, (float4*)p_wo, D_MODEL / 4, D_MODEL / 4);
    round_pack_kernel<<<dim3(D_MODEL, 4), 256>>>(
        (const float4*)w1, (float4*)p_w1, HIDDEN / 4, HIDDEN / 4);
    round_pack_kernel<<<dim3(HIDDEN, 1), 256>>>(
        (const float4*)w2, (float4*)p_w2, D_MODEL / 4, D_MODEL / 4);
    cudaMemcpyAsync(p_bqkv,               bq, D_MODEL * sizeof(float), cudaMemcpyDeviceToDevice, 0);
    cudaMemcpyAsync(p_bqkv + D_MODEL,     bk, D_MODEL * sizeof(float), cudaMemcpyDeviceToDevice, 0);
    cudaMemcpyAsync(p_bqkv + 2 * D_MODEL, bv, D_MODEL * sizeof(float), cudaMemcpyDeviceToDevice, 0);

    // ---- LN1 ----
    ln_kernel<<<M, 256>>>(x, ln1_g, ln1_b, p_h);

    // ---- fused QKV ----
    dim3 gQKV(QKV_LD / 128, M / 128);
    tgemm_kernel<0><<<gQKV, 256, SMEM_BYTES>>>(p_h, p_wqkv, p_bqkv, nullptr,
                                               p_qkv, M, QKV_LD, D_MODEL);

    // ---- sparse attention ----
    sparse_attn_kernel<<<(BATCH * N_HEADS * SEQ) / 4, 128>>>(p_qkv, p_ctx);

    // ---- Wo + residual ----
    dim3 gD(D_MODEL / 128, M / 128);
    tgemm_kernel<1><<<gD, 256, SMEM_BYTES>>>(p_ctx, p_wo, bo, x, p_x1,
                                             M, D_MODEL, D_MODEL);

    // ---- LN2 ----
    ln_kernel<<<M, 256>>>(p_x1, ln2_g, ln2_b, p_h);

    // ---- FFN ----
    dim3 gH(HIDDEN / 128, M / 128);
    tgemm_kernel<2><<<gH, 256, SMEM_BYTES>>>(p_h, p_w1, b1, nullptr, p_ff,
                                             M, HIDDEN, D_MODEL);
    tgemm_kernel<1><<<gD, 256, SMEM_BYTES>>>(p_ff, p_w2, b2, p_x1, out,
                                             M, D_MODEL, HIDDEN);
}

// round 10
// speedup vs baseline: 1.7727x; 1.6397x over previous
#include <cuda_runtime.h>
#include <cuda_fp16.h>
#include <math.h>
#include <stdint.h>

// ---------------------------------------------------------------------------
// GPT Sparse Transformer Block  (B=2, S=2048, D=1024, H=16, Dh=64, HID=4096)
// Round 10 (= Round 9 resubmit after infra failure): fp16 mma.sync.m16n8k16
// GEMMs (fp32 accumulate), 4-stage cp.async, 256 threads / 8 warps (m32n64),
// both operands via ldmatrix. fp16 mantissa == tf32 mantissa (10 bits).
// ---------------------------------------------------------------------------

#define D_MODEL 1024
#define N_HEADS 16
#define HEAD_DIM 64
#define HIDDEN 4096
#define SEQ 2048
#define BATCH 2
#define BLK 16
#define M_ROWS (BATCH * SEQ)   // 4096
#define QKV_LD (3 * D_MODEL)   // 3072

// ------------------------- scratch (no allocations allowed) ----------------
__device__ __half g_h   [M_ROWS * D_MODEL];       // LN output (fp16)
__device__ __half g_qkv [M_ROWS * QKV_LD];        // fused q|k|v (fp16)
__device__ __half g_ctx [M_ROWS * D_MODEL];       // attn out (fp16)
__device__ float  g_x1  [M_ROWS * D_MODEL];       // after attn residual (fp32)
__device__ __half g_ff  [M_ROWS * HIDDEN];        // GELU out (fp16)
// fp16 TRANSPOSED weights [N][K]
__device__ __half g_wqkv[QKV_LD * D_MODEL];
__device__ float  g_bqkv[QKV_LD];
__device__ __half g_wo_t[D_MODEL * D_MODEL];
__device__ __half g_w1_t[HIDDEN * D_MODEL];
__device__ __half g_w2_t[D_MODEL * HIDDEN];

// ------------------------------- helpers -----------------------------------
__device__ __forceinline__ void ldsm_x4(uint32_t* r, uint32_t addr) {
    asm volatile("ldmatrix.sync.aligned.m8n8.x4.shared.b16 {%0,%1,%2,%3}, [%4];"
                 : "=r"(r[0]), "=r"(r[1]), "=r"(r[2]), "=r"(r[3]) : "r"(addr));
}
__device__ __forceinline__ void mma_f16(float* d, const uint32_t* a,
                                        uint32_t b0, uint32_t b1) {
    asm volatile(
        "mma.sync.aligned.m16n8k16.row.col.f32.f16.f16.f32 "
        "{%0,%1,%2,%3}, {%4,%5,%6,%7}, {%8,%9}, {%0,%1,%2,%3};"
        : "+f"(d[0]), "+f"(d[1]), "+f"(d[2]), "+f"(d[3])
        : "r"(a[0]), "r"(a[1]), "r"(a[2]), "r"(a[3]), "r"(b0), "r"(b1));
}
__device__ __forceinline__ void cp16(uint32_t s, const void* g) {
    asm volatile("cp.async.cg.shared.global [%0], [%1], 16;" :: "r"(s), "l"(g));
}
__device__ __forceinline__ void cp_commit() { asm volatile("cp.async.commit_group;"); }

// ----------------- weight transpose + fp16 convert kernel --------------------
// src[K][N] fp32 -> dst[N][K] fp16.  block (32,8), grid (N/32, K/32).
__global__ void __launch_bounds__(256) trt_kernel(
    const float* __restrict__ src, __half* __restrict__ dst, int K, int N)
{
    __shared__ float t[32][33];
    int n0 = blockIdx.x * 32;
    int k0 = blockIdx.y * 32;
    int tx = threadIdx.x, ty = threadIdx.y;
    #pragma unroll
    for (int r = 0; r < 32; r += 8)
        t[ty + r][tx] = src[(size_t)(k0 + ty + r) * N + n0 + tx];
    __syncthreads();
    #pragma unroll
    for (int r = 0; r < 32; r += 8)
        dst[(size_t)(n0 + ty + r) * K + k0 + tx] = __float2half_rn(t[tx][ty + r]);
}

// ------------------------------- LayerNorm ----------------------------------
// fp32 in -> fp16 out (GEMM A operand).
__global__ void __launch_bounds__(256) ln_kernel(
    const float* __restrict__ x, const float* __restrict__ gg,
    const float* __restrict__ bb, __half* __restrict__ out)
{
    __shared__ float red[2][8];
    int row = blockIdx.x;
    int tid = threadIdx.x;
    const float4* xr = reinterpret_cast<const float4*>(x + (size_t)row * D_MODEL);
    float4 v = xr[tid];
    float s  = v.x + v.y + v.z + v.w;
    float sq = v.x*v.x + v.y*v.y + v.z*v.z + v.w*v.w;
    #pragma unroll
    for (int o = 16; o; o >>= 1) {
        s  += __shfl_xor_sync(0xFFFFFFFFu, s,  o);
        sq += __shfl_xor_sync(0xFFFFFFFFu, sq, o);
    }
    if ((tid & 31) == 0) { red[0][tid >> 5] = s; red[1][tid >> 5] = sq; }
    __syncthreads();
    if (tid < 32) {
        float a  = (tid < 8) ? red[0][tid] : 0.f;
        float b2 = (tid < 8) ? red[1][tid] : 0.f;
        #pragma unroll
        for (int o = 4; o; o >>= 1) {
            a  += __shfl_xor_sync(0xFFFFFFFFu, a,  o);
            b2 += __shfl_xor_sync(0xFFFFFFFFu, b2, o);
        }
        if (tid == 0) { red[0][0] = a; red[1][0] = b2; }
    }
    __syncthreads();
    float mean = red[0][0] * (1.f / D_MODEL);
    float var  = red[1][0] * (1.f / D_MODEL) - mean * mean;
    float inv  = rsqrtf(var + 1e-5f);
    float4 g4 = reinterpret_cast<const float4*>(gg)[tid];
    float4 b4 = reinterpret_cast<const float4*>(bb)[tid];
    __half2 h01 = __floats2half2_rn((v.x - mean) * inv * g4.x + b4.x,
                                    (v.y - mean) * inv * g4.y + b4.y);
    __half2 h23 = __floats2half2_rn((v.z - mean) * inv * g4.z + b4.z,
                                    (v.w - mean) * inv * g4.w + b4.w);
    __half2* op = reinterpret_cast<__half2*>(out + (size_t)row * D_MODEL + tid * 4);
    op[0] = h01;
    op[1] = h23;
}

// --------------------------- fp16 tensor GEMM --------------------------------
// C[M,N] = A[M,K] @ Bt^T + bias,  A [M][K] fp16, Bt [N][K] fp16.
// EPI 0: bias -> half out; 1: bias+res -> float out; 2: bias+GELU -> half out.
// Block 128x128x32, 8 warps m32n64, 4-stage cp.async, both operands ldmatrix.
template <int EPI>
__global__ void __launch_bounds__(256, 2) tgemm_kernel(
    const __half* __restrict__ A, const __half* __restrict__ Bt,
    const float* __restrict__ bias, const float* __restrict__ res,
    void* __restrict__ Cv, int M, int N, int K)
{
    constexpr int BM = 128, BN = 128, BK = 32, STAGES = 4;
    constexpr int LDA = 40;                 // halves; 80B rows, conflict-free
    constexpr int TILE = BM * LDA;          // halves per tile
    extern __shared__ __half sm[];
    __half* As = sm;                        // [STAGES][BM][LDA]
    __half* Bs = sm + STAGES * TILE;        // [STAGES][BN][LDA]

    const int tid  = threadIdx.x;
    const int wid  = tid >> 5;
    const int lane = tid & 31;
    const int bm = blockIdx.y * BM;
    const int bn = blockIdx.x * BN;
    const int wm = (wid >> 1) * 32;         // 0,32,64,96
    const int wn = (wid & 1) * 64;          // 0,64

    const int l_row = tid >> 2;             // 0..63 (+64)
    const int l_kc  = (tid & 3) * 8;        // halves
    const __half* Ag = A  + (size_t)(bm + l_row) * K + l_kc;
    const __half* Bg = Bt + (size_t)(bn + l_row) * K + l_kc;
    const uint32_t As_b = (uint32_t)__cvta_generic_to_shared(As);
    const uint32_t Bs_b = (uint32_t)__cvta_generic_to_shared(Bs);

    float acc[2][8][4];
    #pragma unroll
    for (int i = 0; i < 2; i++)
        #pragma unroll
        for (int j = 0; j < 8; j++)
            #pragma unroll
            for (int r = 0; r < 4; r++) acc[i][j][r] = 0.f;

    auto load_stage = [&](int stage, int k0) {
        uint32_t Ad = As_b + (uint32_t)(stage * TILE + l_row * LDA + l_kc) * 2;
        uint32_t Bd = Bs_b + (uint32_t)(stage * TILE + l_row * LDA + l_kc) * 2;
        cp16(Ad,                Ag + k0);
        cp16(Ad + 64 * LDA * 2, Ag + (size_t)64 * K + k0);
        cp16(Bd,                Bg + k0);
        cp16(Bd + 64 * LDA * 2, Bg + (size_t)64 * K + k0);
    };

    const int NIT = K / BK;
    load_stage(0, 0);       cp_commit();
    load_stage(1, BK);      cp_commit();
    load_stage(2, 2 * BK);  cp_commit();

    const int lr = lane & 15;
    const int lh = lane >> 4;

    for (int it = 0; it < NIT; ++it) {
        asm volatile("cp.async.wait_group 2;");
        __syncthreads();
        if (it + 3 < NIT) load_stage((it + 3) & 3, (it + 3) * BK);
        cp_commit();

        const uint32_t a_base = As_b + (uint32_t)((it & 3) * TILE) * 2;
        const uint32_t b_base = Bs_b + (uint32_t)((it & 3) * TILE) * 2;

        #pragma unroll
        for (int ks = 0; ks < 2; ks++) {
            uint32_t af[2][4], bf[4][4];
            #pragma unroll
            for (int mt = 0; mt < 2; mt++)
                ldsm_x4(af[mt], a_base +
                    (uint32_t)((wm + mt * 16 + lr) * LDA + ks * 16 + lh * 8) * 2);
            #pragma unroll
            for (int np = 0; np < 4; np++)
                ldsm_x4(bf[np], b_base +
                    (uint32_t)((wn + np * 16 + lr) * LDA + ks * 16 + lh * 8) * 2);
            #pragma unroll
            for (int mt = 0; mt < 2; mt++) {
                #pragma unroll
                for (int np = 0; np < 4; np++) {
                    mma_f16(acc[mt][2 * np + 0], af[mt], bf[np][0], bf[np][2]);
                    mma_f16(acc[mt][2 * np + 1], af[mt], bf[np][1], bf[np][3]);
                }
            }
        }
        __syncthreads();
    }

    // ---- epilogue ----
    const int qr = lane >> 2;          // 0..7
    const int qc = 2 * (lane & 3);     // 0,2,4,6
    #pragma unroll
    for (int mt = 0; mt < 2; mt++) {
        int r0 = bm + wm + mt * 16 + qr;
        #pragma unroll
        for (int nt = 0; nt < 8; nt++) {
            int col = bn + wn + nt * 8 + qc;
            float2 bv = *reinterpret_cast<const float2*>(&bias[col]);
            float v0 = acc[mt][nt][0] + bv.x;
            float v1 = acc[mt][nt][1] + bv.y;
            float v2 = acc[mt][nt][2] + bv.x;
            float v3 = acc[mt][nt][3] + bv.y;
            if (EPI == 1) {
                const float* R = res;
                float2 r0v = *reinterpret_cast<const float2*>(&R[(size_t)r0 * N + col]);
                float2 r1v = *reinterpret_cast<const float2*>(&R[(size_t)(r0 + 8) * N + col]);
                v0 += r0v.x; v1 += r0v.y; v2 += r1v.x; v3 += r1v.y;
                float* C = (float*)Cv;
                *reinterpret_cast<float2*>(&C[(size_t)r0 * N + col])       = make_float2(v0, v1);
                *reinterpret_cast<float2*>(&C[(size_t)(r0 + 8) * N + col]) = make_float2(v2, v3);
            } else {
                if (EPI == 2) {
                    v0 = 0.5f * v0 * (1.f + erff(v0 * 0.70710678118654752f));
                    v1 = 0.5f * v1 * (1.f + erff(v1 * 0.70710678118654752f));
                    v2 = 0.5f * v2 * (1.f + erff(v2 * 0.70710678118654752f));
                    v3 = 0.5f * v3 * (1.f + erff(v3 * 0.70710678118654752f));
                }
                __half* C = (__half*)Cv;
                *reinterpret_cast<__half2*>(&C[(size_t)r0 * N + col]) =
                    __floats2half2_rn(v0, v1);
                *reinterpret_cast<__half2*>(&C[(size_t)(r0 + 8) * N + col]) =
                    __floats2half2_rn(v2, v3);
            }
        }
    }
}

// ---------------------------- sparse attention ------------------------------
// Reads fused fp16 qkv (row stride 3072). Writes fp16 ctx.
__global__ void __launch_bounds__(128) sparse_attn_kernel(
    const __half* __restrict__ QKV, __half* __restrict__ O)
{
    __shared__ float q_s[4][64];
    __shared__ float p_s[4][160];

    int w    = threadIdx.x >> 5;
    int lane = threadIdx.x & 31;
    int gw   = blockIdx.x * 4 + w;
    int i    = gw & (SEQ - 1);
    int bh   = gw >> 11;
    int h    = bh & (N_HEADS - 1);
    int b    = bh >> 4;

    size_t rowq = (size_t)(b * SEQ + i) * QKV_LD + h * HEAD_DIM;
    q_s[w][lane]      = __half2float(QKV[rowq + lane]);
    q_s[w][lane + 32] = __half2float(QKV[rowq + lane + 32]);
    __syncwarp();

    int lb   = i & ~(BLK - 1);
    int nloc = (i & (BLK - 1)) + 1;
    int nsum = i >> 4;
    int nk   = nloc + nsum;

    float sc[5];
    float mymax = -1e30f;
    #pragma unroll
    for (int c = 0; c < 5; c++) {
        int t = lane + c * 32;
        if (t < nk) {
            int j = (t < nloc) ? (lb + t) : (((t - nloc) << 4) + 15);
            const uint4* kp = reinterpret_cast<const uint4*>(
                QKV + (size_t)(b * SEQ + j) * QKV_LD + D_MODEL + h * HEAD_DIM);
            float dot = 0.f;
            #pragma unroll
            for (int d = 0; d < 8; d++) {        // 8 halves per uint4
                uint4 u = kp[d];
                float2 p0 = __half22float2(*reinterpret_cast<__half2*>(&u.x));
                float2 p1 = __half22float2(*reinterpret_cast<__half2*>(&u.y));
                float2 p2 = __half22float2(*reinterpret_cast<__half2*>(&u.z));
                float2 p3 = __half22float2(*reinterpret_cast<__half2*>(&u.w));
                dot = fmaf(p0.x, q_s[w][d * 8 + 0], dot);
                dot = fmaf(p0.y, q_s[w][d * 8 + 1], dot);
                dot = fmaf(p1.x, q_s[w][d * 8 + 2], dot);
                dot = fmaf(p1.y, q_s[w][d * 8 + 3], dot);
                dot = fmaf(p2.x, q_s[w][d * 8 + 4], dot);
                dot = fmaf(p2.y, q_s[w][d * 8 + 5], dot);
                dot = fmaf(p3.x, q_s[w][d * 8 + 6], dot);
                dot = fmaf(p3.y, q_s[w][d * 8 + 7], dot);
            }
            sc[c] = dot * 0.125f;
            mymax = fmaxf(mymax, sc[c]);
        }
    }
    #pragma unroll
    for (int o = 16; o; o >>= 1)
        mymax = fmaxf(mymax, __shfl_xor_sync(0xFFFFFFFFu, mymax, o));

    float mysum = 0.f;
    #pragma unroll
    for (int c = 0; c < 5; c++) {
        int t = lane + c * 32;
        if (t < nk) { sc[c] = __expf(sc[c] - mymax); mysum += sc[c]; }
    }
    #pragma unroll
    for (int o = 16; o; o >>= 1)
        mysum += __shfl_xor_sync(0xFFFFFFFFu, mysum, o);
    float inv = 1.f / mysum;

    #pragma unroll
    for (int c = 0; c < 5; c++) {
        int t = lane + c * 32;
        if (t < nk) p_s[w][t] = sc[c] * inv;
    }
    __syncwarp();

    float acc0 = 0.f, acc1 = 0.f;
    for (int t = 0; t < nk; t++) {
        int j = (t < nloc) ? (lb + t) : (((t - nloc) << 4) + 15);
        const __half* vp = QKV + (size_t)(b * SEQ + j) * QKV_LD + 2 * D_MODEL + h * HEAD_DIM;
        float p = p_s[w][t];
        acc0 = fmaf(p, __half2float(vp[lane]),      acc0);
        acc1 = fmaf(p, __half2float(vp[lane + 32]), acc1);
    }
    size_t baseo = (size_t)(b * SEQ + i) * D_MODEL + h * HEAD_DIM;
    O[baseo + lane]      = __float2half_rn(acc0);
    O[baseo + lane + 32] = __float2half_rn(acc1);
}

// -------------------------------- launch ------------------------------------
static void* sym_addr(const void* sym) {
    void* p = nullptr;
    cudaGetSymbolAddress(&p, sym);
    return p;
}

extern "C" void kernel_launch(void* const* d_in, const int* in_sizes, int n_in,
                              void* d_out, int out_size)
{
    const float* x     = (const float*)d_in[0];
    const float* ln1_g = (const float*)d_in[1];
    const float* ln1_b = (const float*)d_in[2];
    const float* wq    = (const float*)d_in[3];
    const float* bq    = (const float*)d_in[4];
    const float* wk    = (const float*)d_in[5];
    const float* bk    = (const float*)d_in[6];
    const float* wv    = (const float*)d_in[7];
    const float* bv    = (const float*)d_in[8];
    const float* wo    = (const float*)d_in[9];
    const float* bo    = (const float*)d_in[10];
    const float* ln2_g = (const float*)d_in[11];
    const float* ln2_b = (const float*)d_in[12];
    const float* w1    = (const float*)d_in[13];
    const float* b1    = (const float*)d_in[14];
    const float* w2    = (const float*)d_in[15];
    const float* b2    = (const float*)d_in[16];
    float* out = (float*)d_out;

    __half* p_h    = (__half*)sym_addr(g_h);
    __half* p_qkv  = (__half*)sym_addr(g_qkv);
    __half* p_ctx  = (__half*)sym_addr(g_ctx);
    float*  p_x1   = (float*) sym_addr(g_x1);
    __half* p_ff   = (__half*)sym_addr(g_ff);
    __half* p_wqkv = (__half*)sym_addr(g_wqkv);
    float*  p_bqkv = (float*) sym_addr(g_bqkv);
    __half* p_wo   = (__half*)sym_addr(g_wo_t);
    __half* p_w1   = (__half*)sym_addr(g_w1_t);
    __half* p_w2   = (__half*)sym_addr(g_w2_t);

    const int M = M_ROWS;
    constexpr int SMEM_BYTES = 4 * 2 * 128 * 40 * 2;   // 81,920 B

    cudaFuncSetAttribute(tgemm_kernel<0>, cudaFuncAttributeMaxDynamicSharedMemorySize, SMEM_BYTES);
    cudaFuncSetAttribute(tgemm_kernel<1>, cudaFuncAttributeMaxDynamicSharedMemorySize, SMEM_BYTES);
    cudaFuncSetAttribute(tgemm_kernel<2>, cudaFuncAttributeMaxDynamicSharedMemorySize, SMEM_BYTES);

    // ---- transpose + fp16 weights into [N][K] ----
    dim3 tb(32, 8);
    trt_kernel<<<dim3(D_MODEL / 32, D_MODEL / 32), tb>>>(wq, p_wqkv + 0 * D_MODEL * D_MODEL, D_MODEL, D_MODEL);
    trt_kernel<<<dim3(D_MODEL / 32, D_MODEL / 32), tb>>>(wk, p_wqkv + 1 * D_MODEL * D_MODEL, D_MODEL, D_MODEL);
    trt_kernel<<<dim3(D_MODEL / 32, D_MODEL / 32), tb>>>(wv, p_wqkv + 2 * D_MODEL * D_MODEL, D_MODEL, D_MODEL);
    trt_kernel<<<dim3(D_MODEL / 32, D_MODEL / 32), tb>>>(wo, p_wo, D_MODEL, D_MODEL);
    trt_kernel<<<dim3(HIDDEN / 32,  D_MODEL / 32), tb>>>(w1, p_w1, D_MODEL, HIDDEN);
    trt_kernel<<<dim3(D_MODEL / 32, HIDDEN / 32),  tb>>>(w2, p_w2, HIDDEN, D_MODEL);
    cudaMemcpyAsync(p_bqkv,               bq, D_MODEL * sizeof(float), cudaMemcpyDeviceToDevice, 0);
    cudaMemcpyAsync(p_bqkv + D_MODEL,     bk, D_MODEL * sizeof(float), cudaMemcpyDeviceToDevice, 0);
    cudaMemcpyAsync(p_bqkv + 2 * D_MODEL, bv, D_MODEL * sizeof(float), cudaMemcpyDeviceToDevice, 0);

    // ---- LN1 ----
    ln_kernel<<<M, 256>>>(x, ln1_g, ln1_b, p_h);

    // ---- fused QKV ----
    dim3 gQKV(QKV_LD / 128, M / 128);
    tgemm_kernel<0><<<gQKV, 256, SMEM_BYTES>>>(p_h, p_wqkv, p_bqkv, nullptr,
                                               p_qkv, M, QKV_LD, D_MODEL);

    // ---- sparse attention ----
    sparse_attn_kernel<<<(BATCH * N_HEADS * SEQ) / 4, 128>>>(p_qkv, p_ctx);

    // ---- Wo + residual ----
    dim3 gD(D_MODEL / 128, M / 128);
    tgemm_kernel<1><<<gD, 256, SMEM_BYTES>>>(p_ctx, p_wo, bo, x, p_x1,
                                             M, D_MODEL, D_MODEL);

    // ---- LN2 ----
    ln_kernel<<<M, 256>>>(p_x1, ln2_g, ln2_b, p_h);

    // ---- FFN ----
    dim3 gH(HIDDEN / 128, M / 128);
    tgemm_kernel<2><<<gH, 256, SMEM_BYTES>>>(p_h, p_w1, b1, nullptr, p_ff,
                                             M, HIDDEN, D_MODEL);
    tgemm_kernel<1><<<gD, 256, SMEM_BYTES>>>(p_ff, p_w2, b2, p_x1, out,
                                             M, D_MODEL, HIDDEN);
}